// round 10
// baseline (speedup 1.0000x reference)
#include <cuda_runtime.h>
#include <math.h>

#define BB 64
#define TT 512
#define II 256
#define OO 1024
#define MM 8
#define IMM 2048
#define NBLK 148
#define NT 1024
#define KSR 12                 // REC k-splits per tile (k-chunk 192)
#define KSA 8                  // ACT k-splits per tile (k-chunk 160)
#define NRECT 8                // REC tiles of 256 cols
#define NACTT 4                // ACT tiles of 256 cols
#define NREC (NRECT * KSR)     // 96
#define NACT (NACTT * KSA)     // 32
#define NGEMM (NREC + NACT)    // 128
#define NGATE 16
#define GATE0 NGEMM            // 128..143
#define RELEASER 147
// smem: sB[2][16][256] + sA_dup[2][16][128]  (floats) = 48 KB
#define SB_FLOATS (2 * 16 * 256)
#define SA_FLOATS (2 * 16 * 128)
#define DYN_SMEM ((SB_FLOATS + SA_FLOATS) * 4)

// ---------------- persistent device state ------------------------------------
__device__ float g_H[BB * OO];             // h carry
__device__ float g_XP[BB * IMM];           // x_pred carry
__device__ float g_Pact[KSA][BB * OO];     // split-K partials (acts)
__device__ float g_Prec[KSR][BB * IMM];    // split-K partials (acts_rec)
__device__ float g_lse[IMM];
__device__ float g_gate[BB * MM];
__device__ volatile unsigned g_garr[NGATE];   // gate mini-barrier
__device__ volatile unsigned g_ggen;
__device__ volatile unsigned g_arr[NBLK];     // grid arrival flags
__device__ volatile unsigned g_gen;           // grid release gen

// ---------------- grid barrier (monotonic, replay-safe) ----------------------
__device__ __forceinline__ void grid_arrive(unsigned tgt) {
    __syncthreads();
    if (threadIdx.x == 0) { __threadfence(); g_arr[blockIdx.x] = tgt; }
}
__device__ __forceinline__ void grid_wait(unsigned tgt) {
    const int tid = threadIdx.x;
    if (blockIdx.x == RELEASER) {
        if (tid < NBLK) { while ((int)(g_arr[tid] - tgt) < 0) {} }
        __syncthreads();
        if (tid == 0) { __threadfence(); g_gen = tgt; }
    } else {
        if (tid == 0) {
            while ((int)(g_gen - tgt) < 0) { __nanosleep(32); }
            __threadfence();
        }
    }
    __syncthreads();
}

// ---------------- packed f32x2 helpers ---------------------------------------
__device__ __forceinline__ void ffma2(unsigned long long& d, unsigned long long a,
                                      unsigned long long b) {
    asm("fma.rn.f32x2 %0, %1, %2, %0;" : "+l"(d) : "l"(a), "l"(b));
}

// Dup-paired A float-offset for batch b within a 128-float k-row:
// [bgrp(2) x 64][half(2) x 32][qb(8) x 4]; pairs of batches per 16B granule.
__device__ __forceinline__ int dupoff(int b) {
    return (b >> 5) * 64 + ((b & 3) >> 1) * 32 + ((b >> 2) & 7) * 4 + (b & 1) * 2;
}

// ---------------- 64x256-tile GEMM chunk (NT=1024, 4b x 4c threads) ----------
// P[b][col0+c] = sum_{k in [k0, k0+16*nsub)} A[b][k] * W(col,k)
// A[b][k] = xb[b*xs+k] (k<II) else cb[b*cs+(k-II)] (cross-SM carry -> ldcg)
// W(c,k)  = W1[c*ld1+k] (k<II) else W2[c*ld2+(k-II)]
__device__ __forceinline__ void gemm_unit(
    const float* xb, int xs, const float* cb, int cs,
    const float* __restrict__ W1, int ld1,
    const float* __restrict__ W2, int ld2,
    int col0, int k0, int nsub,
    float* __restrict__ P, int NC, float* dynsh)
{
    float* sB = dynsh;                 // [2][16][256] k-major W
    float* sA = dynsh + SB_FLOATS;     // [2][16][128] dup-paired A
    const int tid = threadIdx.x;
    const int wid = tid >> 5, lane = tid & 31;
    // compute roles: 32 warps = 2 bgrp x 16 cgrp; lane = 8 qb x 4 qc
    const int bgrp = wid & 1;
    const int cgrp = wid >> 1;
    const int qb = lane >> 2;
    const int qc = lane & 3;
    const int aoff = bgrp * 64 + qb * 4;     // + half*32 for batches 2,3
    const int woff = cgrp * 16 + qc * 4;
    // W stager: all 1024 threads, 1 float4 each per chunk
    const int jc = tid & 255;                // W row (col) to stage
    const int kh4 = (tid >> 8) * 4;          // k sub-quad 0/4/8/12
    // A stager: tid < 256
    const int sb_b = tid & 63;
    const int sb_kq = (tid >> 6) & 3;
    const int sa_off = dupoff(sb_b);

    unsigned long long acc[4][2];            // [batch i][col pair]
#pragma unroll
    for (int i = 0; i < 4; i++) { acc[i][0] = 0ull; acc[i][1] = 0ull; }

    const int j = col0 + jc;
    float4 wbuf, abuf;
    {   // prefetch chunk 0
        const int kb = k0;
        const float* ws = (kb < II) ? (W1 + (size_t)j * ld1 + kb)
                                    : (W2 + (size_t)j * ld2 + (kb - II));
        wbuf = __ldg((const float4*)(ws + kh4));
        if (tid < 256) {
            const float* as = (kb < II) ? (xb + sb_b * xs + kb + sb_kq * 4)
                                        : (cb + sb_b * cs + (kb - II) + sb_kq * 4);
            abuf = __ldcg((const float4*)as);
        }
    }
    {   // stage chunk 0 into buffer 0
        sB[(kh4 + 0) * 256 + jc] = wbuf.x;
        sB[(kh4 + 1) * 256 + jc] = wbuf.y;
        sB[(kh4 + 2) * 256 + jc] = wbuf.z;
        sB[(kh4 + 3) * 256 + jc] = wbuf.w;
        if (tid < 256) {
            float* d = sA + (sb_kq * 4) * 128 + sa_off;
            *(float2*)(d)       = make_float2(abuf.x, abuf.x);
            *(float2*)(d + 128) = make_float2(abuf.y, abuf.y);
            *(float2*)(d + 256) = make_float2(abuf.z, abuf.z);
            *(float2*)(d + 384) = make_float2(abuf.w, abuf.w);
        }
    }
    __syncthreads();

    for (int s = 0; s < nsub; s++) {
        const float* sBb = sB + (s & 1) * (16 * 256);
        const float* sAb = sA + (s & 1) * (16 * 128);

        if (s + 1 < nsub) {   // prefetch next chunk under compute
            const int kb = k0 + (s + 1) * 16;
            const float* ws = (kb < II) ? (W1 + (size_t)j * ld1 + kb)
                                        : (W2 + (size_t)j * ld2 + (kb - II));
            wbuf = __ldg((const float4*)(ws + kh4));
            if (tid < 256) {
                const float* as = (kb < II) ? (xb + sb_b * xs + kb + sb_kq * 4)
                                            : (cb + sb_b * cs + (kb - II) + sb_kq * 4);
                abuf = __ldcg((const float4*)as);
            }
        }

        // 16-k compute: 3 single-wavefront LDS.128 + 8 FFMA2 per k per thread
#pragma unroll
        for (int k = 0; k < 16; k++) {
            const float* pa = sAb + k * 128 + aoff;
            ulonglong2 av0 = *(const ulonglong2*)(pa);        // dup(b0),dup(b1)
            ulonglong2 av1 = *(const ulonglong2*)(pa + 32);   // dup(b2),dup(b3)
            ulonglong2 wv  = *(const ulonglong2*)(sBb + k * 256 + woff);
            ffma2(acc[0][0], av0.x, wv.x); ffma2(acc[0][1], av0.x, wv.y);
            ffma2(acc[1][0], av0.y, wv.x); ffma2(acc[1][1], av0.y, wv.y);
            ffma2(acc[2][0], av1.x, wv.x); ffma2(acc[2][1], av1.x, wv.y);
            ffma2(acc[3][0], av1.y, wv.x); ffma2(acc[3][1], av1.y, wv.y);
        }

        if (s + 1 < nsub) {   // stage next chunk into the other buffer
            float* sBd = sB + ((s + 1) & 1) * (16 * 256);
            float* sAd = sA + ((s + 1) & 1) * (16 * 128);
            sBd[(kh4 + 0) * 256 + jc] = wbuf.x;
            sBd[(kh4 + 1) * 256 + jc] = wbuf.y;
            sBd[(kh4 + 2) * 256 + jc] = wbuf.z;
            sBd[(kh4 + 3) * 256 + jc] = wbuf.w;
            if (tid < 256) {
                float* d = sAd + (sb_kq * 4) * 128 + sa_off;
                *(float2*)(d)       = make_float2(abuf.x, abuf.x);
                *(float2*)(d + 128) = make_float2(abuf.y, abuf.y);
                *(float2*)(d + 256) = make_float2(abuf.z, abuf.z);
                *(float2*)(d + 384) = make_float2(abuf.w, abuf.w);
            }
        }
        __syncthreads();
    }

    // write partial tile: thread owns 4 batches x 4 cols
#pragma unroll
    for (int i = 0; i < 4; i++) {
        const int b = bgrp * 32 + qb * 4 + i;
        ulonglong2 v; v.x = acc[i][0]; v.y = acc[i][1];
        *(ulonglong2*)(P + (size_t)b * NC + col0 + cgrp * 16 + qc * 4) = v;
    }
}

// ---------------- gate work (16 CTAs), overlapped with GEMM phase -------------
__device__ __forceinline__ void gate_work(
    int t, const float* __restrict__ XPold, const float* __restrict__ x,
    const float* __restrict__ periods, const float* __restrict__ shifts,
    float* __restrict__ out_ps, unsigned tgt)
{
    const int gi = blockIdx.x - GATE0;       // 0..15
    const int tid = threadIdx.x, wid = tid >> 5, lane = tid & 31;

    // pass 1: batch-axis logsumexp for 128 cols (32 warps, 4 cols each)
#pragma unroll
    for (int it = 0; it < 4; it++) {
        const int col = gi * 128 + it * 32 + wid;
        float v0 = __ldcg(&XPold[lane * IMM + col]);
        float v1 = __ldcg(&XPold[(lane + 32) * IMM + col]);
        float m = fmaxf(v0, v1);
#pragma unroll
        for (int off = 16; off > 0; off >>= 1)
            m = fmaxf(m, __shfl_xor_sync(0xffffffffu, m, off));
        float s = expf(v0 - m) + expf(v1 - m);
#pragma unroll
        for (int off = 16; off > 0; off >>= 1)
            s += __shfl_xor_sync(0xffffffffu, s, off);
        if (lane == 0) g_lse[col] = m + logf(s);
    }
    // mini-barrier among the 16 gate CTAs
    __syncthreads();
    if (tid == 0) { __threadfence(); g_garr[gi] = tgt; }
    if (gi == 0) {
        if (tid < NGATE) { while ((int)(g_garr[tid] - tgt) < 0) {} }
        __syncthreads();
        if (tid == 0) { __threadfence(); g_ggen = tgt; }
        __syncthreads();
    } else {
        if (tid == 0) { while ((int)(g_ggen - tgt) < 0) {} __threadfence(); }
        __syncthreads();
    }
    // pass 2: surprisal -> mp -> gate, 1 (b,m) pair per warp (32 of 512)
    {
        const int u = gi * 32 + wid;
        const int b = u >> 3, mo = u & 7;
        float s = 0.f;
#pragma unroll
        for (int i0 = 0; i0 < II; i0 += 32) {
            const int i = i0 + lane;
            s += (__ldcg(&XPold[b * IMM + mo * II + i]) - __ldcg(&g_lse[mo * II + i]))
                 * __ldg(&x[((size_t)b * TT + t) * II + i]);
        }
#pragma unroll
        for (int off = 16; off > 0; off >>= 1)
            s += __shfl_xor_sync(0xffffffffu, s, off);
        if (lane == 0) {
            const float mp = s * (1.f / (float)II) * __ldg(&periods[mo]);
            out_ps[((size_t)b * TT + t) * MM + mo] = mp;
            g_gate[u] = (sinf((float)t * mp + __ldg(&shifts[mo])) + 1.f) * 0.5f;
        }
    }
}

// ---------------- persistent kernel ------------------------------------------
__global__ void __launch_bounds__(NT, 1)
cwrnn_kernel(const float* __restrict__ x, const float* __restrict__ W_in,
             const float* __restrict__ b_in, const float* __restrict__ W_h,
             const float* __restrict__ W_ir, const float* __restrict__ b_ir,
             const float* __restrict__ W_hr, const float* __restrict__ periods,
             const float* __restrict__ shifts, float* __restrict__ out)
{
    extern __shared__ float dynsh[];
    const int bid = blockIdx.x, tid = threadIdx.x;
    const int gstep = NBLK * NT;
    float* out_ys = out;
    float* out_hf = out + (size_t)BB * TT * OO;
    float* out_ps = out_hf + BB * OO;

    const unsigned base = g_gen;   // monotonic across graph replays

    for (int idx = bid * NT + tid; idx < BB * OO; idx += gstep) g_H[idx] = 0.f;
    for (int idx = bid * NT + tid; idx < BB * IMM; idx += gstep) g_XP[idx] = 0.f;
    grid_arrive(base + 1);
    grid_wait(base + 1);

    for (int t = 0; t < TT; t++) {
        const unsigned tgtA = base + 2 + 2 * t;
        const unsigned tgtB = base + 3 + 2 * t;
        const float* xb = x + (size_t)t * II;

        // ===== phase A: GEMM partials || gate ================================
        if (bid < NREC) {
            const int tile = bid / KSR, ks = bid - tile * KSR;
            gemm_unit(xb, TT * II, g_XP, IMM, W_ir, II, W_hr, IMM,
                      tile * 256, ks * 192, 12, g_Prec[ks], IMM, dynsh);
        } else if (bid < NGEMM) {
            const int v = bid - NREC, tile = v / KSA, ks = v - tile * KSA;
            gemm_unit(xb, TT * II, g_H, OO, W_in, II, W_h, OO,
                      tile * 256, ks * 160, 10, g_Pact[ks], OO, dynsh);
        } else if (bid < GATE0 + NGATE) {
            gate_work(t, g_XP, x, periods, shifts, out_ps, tgtA);
        }
        grid_arrive(tgtA);
        grid_wait(tgtA);

        // ===== phase B: reduce split-K, tanh, blend, outputs (all CTAs) ======
        const int TOTB = BB * IMM + BB * OO;
        for (int idx = bid * NT + tid; idx < TOTB; idx += gstep) {
            if (idx < BB * IMM) {
                const int b = idx >> 11, jj = idx & (IMM - 1);
                float s = __ldg(&b_ir[jj]);
#pragma unroll
                for (int k2 = 0; k2 < KSR; k2++)
                    s += __ldcg(&g_Prec[k2][b * IMM + jj]);
                g_XP[b * IMM + jj] = tanhf(s);
            } else {
                const int i2 = idx - BB * IMM;
                const int b = i2 >> 10, o = i2 & (OO - 1);
                float s = __ldg(&b_in[o]);
#pragma unroll
                for (int k2 = 0; k2 < KSA; k2++)
                    s += __ldcg(&g_Pact[k2][b * OO + o]);
                const float a = tanhf(s);
                const float g = __ldcg(&g_gate[b * MM + (o >> 7)]);
                const float h = g_H[b * OO + o];
                const float y = (1.f - g) * a + g * h;
                out_ys[((size_t)b * TT + t) * OO + o] = y;
                g_H[b * OO + o] = y;
                if (t == TT - 1) out_hf[b * OO + o] = y;
            }
        }
        grid_arrive(tgtB);
        grid_wait(tgtB);
    }
}

extern "C" void kernel_launch(void* const* d_in, const int* in_sizes, int n_in,
                              void* d_out, int out_size) {
    (void)in_sizes; (void)n_in; (void)out_size;
    const float* x       = (const float*)d_in[0];
    const float* W_in    = (const float*)d_in[1];
    const float* b_in    = (const float*)d_in[2];
    const float* W_h     = (const float*)d_in[3];
    const float* W_ir    = (const float*)d_in[4];
    const float* b_ir    = (const float*)d_in[5];
    const float* W_hr    = (const float*)d_in[6];
    const float* periods = (const float*)d_in[7];
    const float* shifts  = (const float*)d_in[8];
    float* out = (float*)d_out;

    cudaFuncSetAttribute(cwrnn_kernel,
                         cudaFuncAttributeMaxDynamicSharedMemorySize, DYN_SMEM);
    cwrnn_kernel<<<NBLK, NT, DYN_SMEM>>>(x, W_in, b_in, W_h, W_ir, b_ir, W_hr,
                                         periods, shifts, out);
}

// round 15
// speedup vs baseline: 1.7795x; 1.7795x over previous
#include <cuda_runtime.h>
#include <cuda_bf16.h>
#include <math.h>

#define BB 64
#define TT 512
#define II 256
#define OO 1024
#define MM 8
#define IMM 2048
#define KR 2304
#define KA 1280
#define NBLK 148
#define NT 256
#define KSR 6                  // REC K'-splits (K'=4608, chunk 768)
#define KSA 4                  // ACT K'-splits (K'=2560, chunk 640)
#define NREC 96                // 16 tiles x 6 splits
#define NACT 32                // 8 tiles x 4 splits
#define NGEMM 128
#define NGATE 16
#define GATE0 128
#define RELEASER 147
#define SMEM_A 0               // A tile: 128 rows x 128B = 16384
#define SMEM_B 16384           // B tile: 128 cols x 128B = 16384
#define DYN_SMEM 32768
#define SWZ(o) ((o) ^ (((o) >> 3) & 0x70))
#define SPIN_BUDGET 4000000000LL

// ---------------- persistent device state ------------------------------------
__device__ __align__(128) __nv_bfloat16 g_Wrh[2048 * KR], g_Wrl[2048 * KR];
__device__ __align__(128) __nv_bfloat16 g_Wah[1024 * KA], g_Wal[1024 * KA];
__device__ __align__(128) __nv_bfloat16 g_xh[TT * BB * II], g_xl[TT * BB * II];
__device__ __align__(128) __nv_bfloat16 g_XPh[BB * IMM], g_XPl[BB * IMM];
__device__ __align__(128) __nv_bfloat16 g_Hh[BB * OO], g_Hl[BB * OO];
__device__ float g_XP[BB * IMM];           // fp32 x_pred carry (gate path)
__device__ float g_H[BB * OO];             // fp32 h carry
__device__ float g_Prec[KSR][128 * IMM];   // 128 rows: [hi(64); lo(64)]
__device__ float g_Pact[KSA][128 * OO];
__device__ float g_lse[IMM];
__device__ float g_gate[BB * MM];
__device__ volatile unsigned g_garr[NGATE];
__device__ volatile unsigned g_ggen;
__device__ volatile unsigned g_arr[NBLK];
__device__ volatile unsigned g_gen;

// ---------------- bounded spin (deadlock -> wrong answer, not container kill) -
__device__ __forceinline__ void spin_until(volatile unsigned* p, unsigned tgt) {
    long long t0 = clock64();
    while ((int)(*p - tgt) < 0) {
        if (clock64() - t0 > SPIN_BUDGET) break;
        __nanosleep(32);
    }
}

// ---------------- grid barrier (monotonic, replay-safe) ----------------------
__device__ __forceinline__ void grid_arrive(unsigned tgt) {
    __syncthreads();
    if (threadIdx.x == 0) { __threadfence(); g_arr[blockIdx.x] = tgt; }
}
__device__ __forceinline__ void grid_wait(unsigned tgt) {
    const int tid = threadIdx.x;
    if (blockIdx.x == RELEASER) {
        if (tid < NBLK) spin_until(&g_arr[tid], tgt);
        __syncthreads();
        if (tid == 0) { __threadfence(); g_gen = tgt; }
    } else {
        if (tid == 0) { spin_until(&g_gen, tgt); __threadfence(); }
    }
    __syncthreads();
}

// ---------------- warp-MMA helpers -------------------------------------------
__device__ __forceinline__ unsigned smem_u32(const void* p) {
    unsigned a;
    asm("{ .reg .u64 t; cvta.to.shared.u64 t, %1; cvt.u32.u64 %0, t; }"
        : "=r"(a) : "l"(p));
    return a;
}
__device__ __forceinline__ void ldsm4(unsigned* r, unsigned addr) {
    asm volatile("ldmatrix.sync.aligned.m8n8.x4.shared.b16 {%0,%1,%2,%3}, [%4];"
                 : "=r"(r[0]), "=r"(r[1]), "=r"(r[2]), "=r"(r[3]) : "r"(addr));
}
__device__ __forceinline__ void mma16816(float* c, const unsigned* a,
                                         const unsigned* b) {
    asm volatile(
        "mma.sync.aligned.m16n8k16.row.col.f32.bf16.bf16.f32 "
        "{%0,%1,%2,%3}, {%4,%5,%6,%7}, {%8,%9}, {%0,%1,%2,%3};"
        : "+f"(c[0]), "+f"(c[1]), "+f"(c[2]), "+f"(c[3])
        : "r"(a[0]), "r"(a[1]), "r"(a[2]), "r"(a[3]), "r"(b[0]), "r"(b[1]));
}

// ---------------- split-bf16 warp-MMA GEMM step ------------------------------
// D[128 rows = [hi A; lo A]][128 cols] over this CTA's K' chunk -> P (fp32).
__device__ __forceinline__ void gemm_step(
    int nsub, int kb0,
    const __nv_bfloat16* __restrict__ Wsel, int Ktot,
    const __nv_bfloat16* __restrict__ xh_t, const __nv_bfloat16* __restrict__ xl_t,
    const __nv_bfloat16* __restrict__ Ch, const __nv_bfloat16* __restrict__ Cl,
    int ldc, int col0, float* __restrict__ P, int NC,
    unsigned smem_base, char* smem)
{
    const int tid = threadIdx.x, wid = tid >> 5, lane = tid & 31;
    const int wm = wid & 3, wn = wid >> 2;       // 4 m-groups x 2 n-groups
    // staging roles (256 threads: A 128 rows x 2 halves; B 128 cols x 2 halves)
    const int arow = tid >> 1, ach = (tid & 1) * 32;
    const int r = arow & 63;
    const bool lorow = arow >= 64;
    const int bcol = tid >> 1, bkh = (tid & 1) * 32;
    // ldmatrix pre-swizzle byte offsets
    const unsigned aOff0 = (unsigned)((wm * 32 + (lane & 15)) * 128 + (lane >> 4) * 16);
    const unsigned aOff1 = aOff0 + 16 * 128;
    const int lg = lane >> 3;
    unsigned bOff[4];
#pragma unroll
    for (int np = 0; np < 4; np++) {
        const int nl = wn * 64 + np * 16 + ((lg & 2) << 2) + (lane & 7);
        bOff[np] = (unsigned)(nl * 128 + (lg & 1) * 16);
    }

    float acc[2][8][4];
#pragma unroll
    for (int mt = 0; mt < 2; mt++)
#pragma unroll
        for (int nt = 0; nt < 8; nt++)
#pragma unroll
            for (int q = 0; q < 4; q++) acc[mt][nt][q] = 0.f;

    uint4 pva[4], pvb[4];
    {   // prefetch sub-chunk 0
        const int kb = kb0;
        const __nv_bfloat16* asrc = (kb < II)
            ? ((lorow ? xl_t : xh_t) + r * II + kb + ach)
            : ((lorow ? Cl : Ch) + (size_t)r * ldc + (kb - II) + ach);
        const __nv_bfloat16* bsrc = Wsel + (size_t)(col0 + bcol) * Ktot + kb + bkh;
#pragma unroll
        for (int j = 0; j < 4; j++) {
            pva[j] = __ldcg((const uint4*)(asrc + j * 8));
            pvb[j] = __ldg((const uint4*)(bsrc + j * 8));
        }
    }

    for (int c = 0; c < nsub; c++) {
        // commit staged regs to smem (SW128 swizzle)
#pragma unroll
        for (int j = 0; j < 4; j++) {
            *(uint4*)(smem + SMEM_A + SWZ((unsigned)(arow * 128 + ach * 2 + j * 16))) = pva[j];
            *(uint4*)(smem + SMEM_B + SWZ((unsigned)(bcol * 128 + bkh * 2 + j * 16))) = pvb[j];
        }
        __syncthreads();

        if (c + 1 < nsub) {   // prefetch next sub-chunk under MMA
            const int kb = kb0 + (c + 1) * 64;
            const __nv_bfloat16* asrc = (kb < II)
                ? ((lorow ? xl_t : xh_t) + r * II + kb + ach)
                : ((lorow ? Cl : Ch) + (size_t)r * ldc + (kb - II) + ach);
            const __nv_bfloat16* bsrc = Wsel + (size_t)(col0 + bcol) * Ktot + kb + bkh;
#pragma unroll
            for (int j = 0; j < 4; j++) {
                pva[j] = __ldcg((const uint4*)(asrc + j * 8));
                pvb[j] = __ldg((const uint4*)(bsrc + j * 8));
            }
        }

        // 4 k-steps of 16: 6 ldmatrix + 16 mma per warp per k-step
#pragma unroll
        for (int kst = 0; kst < 4; kst++) {
            unsigned a0[4], a1[4], bb[4][4];
            ldsm4(a0, smem_base + SMEM_A + SWZ(aOff0 + kst * 32));
            ldsm4(a1, smem_base + SMEM_A + SWZ(aOff1 + kst * 32));
#pragma unroll
            for (int np = 0; np < 4; np++)
                ldsm4(bb[np], smem_base + SMEM_B + SWZ(bOff[np] + kst * 32));
#pragma unroll
            for (int np = 0; np < 4; np++) {
                mma16816(acc[0][2 * np],     a0, &bb[np][0]);
                mma16816(acc[0][2 * np + 1], a0, &bb[np][2]);
                mma16816(acc[1][2 * np],     a1, &bb[np][0]);
                mma16816(acc[1][2 * np + 1], a1, &bb[np][2]);
            }
        }
        __syncthreads();
    }

    // write partials: C frag layout (m16n8): c0,c1 -> row=lane>>2, col=(lane&3)*2
    const int rr = lane >> 2, cc = (lane & 3) * 2;
#pragma unroll
    for (int mt = 0; mt < 2; mt++)
#pragma unroll
        for (int nt = 0; nt < 8; nt++) {
            const int row = wm * 32 + mt * 16 + rr;
            const int col = col0 + wn * 64 + nt * 8 + cc;
            float* p0 = P + (size_t)row * NC + col;
            *(float2*)p0 = make_float2(acc[mt][nt][0], acc[mt][nt][1]);
            *(float2*)(p0 + 8 * NC) = make_float2(acc[mt][nt][2], acc[mt][nt][3]);
        }
}

// ---------------- gate work (16 CTAs, NT=256) --------------------------------
__device__ __forceinline__ void gate_work(
    int t, const float* __restrict__ XPold, const float* __restrict__ x,
    const float* __restrict__ periods, const float* __restrict__ shifts,
    float* __restrict__ out_ps, unsigned tgt)
{
    const int gi = blockIdx.x - GATE0;
    const int tid = threadIdx.x, wid = tid >> 5, lane = tid & 31;
#pragma unroll
    for (int it = 0; it < 16; it++) {
        const int col = gi * 128 + it * 8 + wid;
        float v0 = __ldcg(&XPold[lane * IMM + col]);
        float v1 = __ldcg(&XPold[(lane + 32) * IMM + col]);
        float m = fmaxf(v0, v1);
#pragma unroll
        for (int off = 16; off > 0; off >>= 1)
            m = fmaxf(m, __shfl_xor_sync(0xffffffffu, m, off));
        float s = expf(v0 - m) + expf(v1 - m);
#pragma unroll
        for (int off = 16; off > 0; off >>= 1)
            s += __shfl_xor_sync(0xffffffffu, s, off);
        if (lane == 0) g_lse[col] = m + logf(s);
    }
    __syncthreads();
    if (tid == 0) { __threadfence(); g_garr[gi] = tgt; }
    if (gi == 0) {
        if (tid < NGATE) spin_until(&g_garr[tid], tgt);
        __syncthreads();
        if (tid == 0) { __threadfence(); g_ggen = tgt; }
        __syncthreads();
    } else {
        if (tid == 0) { spin_until(&g_ggen, tgt); __threadfence(); }
        __syncthreads();
    }
#pragma unroll
    for (int uu = 0; uu < 4; uu++) {
        const int u = gi * 32 + wid * 4 + uu;
        const int b = u >> 3, mo = u & 7;
        float s = 0.f;
#pragma unroll
        for (int i0 = 0; i0 < II; i0 += 32) {
            const int i = i0 + lane;
            s += (__ldcg(&XPold[b * IMM + mo * II + i]) - __ldcg(&g_lse[mo * II + i]))
                 * __ldg(&x[((size_t)b * TT + t) * II + i]);
        }
#pragma unroll
        for (int off = 16; off > 0; off >>= 1)
            s += __shfl_xor_sync(0xffffffffu, s, off);
        if (lane == 0) {
            const float mp = s * (1.f / (float)II) * __ldg(&periods[mo]);
            out_ps[((size_t)b * TT + t) * MM + mo] = mp;
            g_gate[u] = (sinf((float)t * mp + __ldg(&shifts[mo])) + 1.f) * 0.5f;
        }
    }
}

// ---------------- persistent kernel ------------------------------------------
__global__ void __launch_bounds__(NT, 1)
cwrnn_kernel(const float* __restrict__ x, const float* __restrict__ W_in,
             const float* __restrict__ b_in, const float* __restrict__ W_h,
             const float* __restrict__ W_ir, const float* __restrict__ b_ir,
             const float* __restrict__ W_hr, const float* __restrict__ periods,
             const float* __restrict__ shifts, float* __restrict__ out)
{
    extern __shared__ char smem[];
    const unsigned smem_base = smem_u32(smem);
    const int bid = blockIdx.x, tid = threadIdx.x;
    const int gtid = bid * NT + tid, G = NBLK * NT;
    float* out_ys = out;
    float* out_hf = out + (size_t)BB * TT * OO;
    float* out_ps = out_hf + BB * OO;

    const unsigned base = g_gen;

    // ===== init: split weights/x to bf16 hi/lo, zero carries ================
    for (int idx = gtid; idx < 2048 * KR; idx += G) {
        const int n = idx / KR, k = idx - n * KR;
        const float v = (k < II) ? W_ir[n * II + k] : W_hr[(size_t)n * IMM + (k - II)];
        const __nv_bfloat16 h = __float2bfloat16(v);
        g_Wrh[idx] = h;
        g_Wrl[idx] = __float2bfloat16(v - __bfloat162float(h));
    }
    for (int idx = gtid; idx < 1024 * KA; idx += G) {
        const int n = idx / KA, k = idx - n * KA;
        const float v = (k < II) ? W_in[n * II + k] : W_h[(size_t)n * OO + (k - II)];
        const __nv_bfloat16 h = __float2bfloat16(v);
        g_Wah[idx] = h;
        g_Wal[idx] = __float2bfloat16(v - __bfloat162float(h));
    }
    for (int idx = gtid; idx < TT * BB * II; idx += G) {
        const int t = idx / (BB * II), rem = idx - t * BB * II;
        const int b = rem >> 8, i = rem & 255;
        const float v = x[(size_t)b * TT * II + t * II + i];
        const __nv_bfloat16 h = __float2bfloat16(v);
        g_xh[idx] = h;
        g_xl[idx] = __float2bfloat16(v - __bfloat162float(h));
    }
    for (int idx = gtid; idx < BB * IMM; idx += G) {
        g_XP[idx] = 0.f;
        g_XPh[idx] = __float2bfloat16(0.f);
        g_XPl[idx] = __float2bfloat16(0.f);
    }
    for (int idx = gtid; idx < BB * OO; idx += G) {
        g_H[idx] = 0.f;
        g_Hh[idx] = __float2bfloat16(0.f);
        g_Hl[idx] = __float2bfloat16(0.f);
    }
    grid_arrive(base + 1);
    grid_wait(base + 1);

    for (int t = 0; t < TT; t++) {
        const unsigned tgtA = base + 2 + 2 * t;
        const unsigned tgtB = base + 3 + 2 * t;
        const __nv_bfloat16* xh_t = g_xh + (size_t)t * BB * II;
        const __nv_bfloat16* xl_t = g_xl + (size_t)t * BB * II;

        // ===== phase A: warp-MMA GEMM partials || gate ======================
        if (bid < NREC) {
            const int tile = bid / KSR, ks = bid - tile * KSR;
            const int kb0 = (ks % 3) * 768;
            gemm_step(12, kb0, (ks < 3) ? g_Wrh : g_Wrl, KR, xh_t, xl_t,
                      g_XPh, g_XPl, IMM, tile * 128, g_Prec[ks], IMM,
                      smem_base, smem);
        } else if (bid < NGEMM) {
            const int v = bid - NREC, tile = v / KSA, ks = v - tile * KSA;
            const int kb0 = (ks % 2) * 640;
            gemm_step(10, kb0, (ks < 2) ? g_Wah : g_Wal, KA, xh_t, xl_t,
                      g_Hh, g_Hl, OO, tile * 128, g_Pact[ks], OO,
                      smem_base, smem);
        } else if (bid < GATE0 + NGATE) {
            gate_work(t, g_XP, x, periods, shifts, out_ps, tgtA);
        }
        grid_arrive(tgtA);
        grid_wait(tgtA);

        // ===== phase B: reduce (hi+lo rows, splits), tanh, blend ============
        const int TOTB = BB * IMM + BB * OO;
        for (int idx = gtid; idx < TOTB; idx += G) {
            if (idx < BB * IMM) {
                const int b = idx >> 11, jj = idx & (IMM - 1);
                float s = __ldg(&b_ir[jj]);
#pragma unroll
                for (int k2 = 0; k2 < KSR; k2++)
                    s += __ldcg(&g_Prec[k2][(size_t)b * IMM + jj])
                       + __ldcg(&g_Prec[k2][(size_t)(b + 64) * IMM + jj]);
                const float v = tanhf(s);
                g_XP[b * IMM + jj] = v;
                const __nv_bfloat16 h = __float2bfloat16(v);
                g_XPh[b * IMM + jj] = h;
                g_XPl[b * IMM + jj] = __float2bfloat16(v - __bfloat162float(h));
            } else {
                const int i2 = idx - BB * IMM;
                const int b = i2 >> 10, o = i2 & (OO - 1);
                float s = __ldg(&b_in[o]);
#pragma unroll
                for (int k2 = 0; k2 < KSA; k2++)
                    s += __ldcg(&g_Pact[k2][(size_t)b * OO + o])
                       + __ldcg(&g_Pact[k2][(size_t)(b + 64) * OO + o]);
                const float a = tanhf(s);
                const float g = __ldcg(&g_gate[b * MM + (o >> 7)]);
                const float hprev = __ldcg(&g_H[b * OO + o]);
                const float y = (1.f - g) * a + g * hprev;
                out_ys[((size_t)b * TT + t) * OO + o] = y;
                g_H[b * OO + o] = y;
                const __nv_bfloat16 hh = __float2bfloat16(y);
                g_Hh[b * OO + o] = hh;
                g_Hl[b * OO + o] = __float2bfloat16(y - __bfloat162float(hh));
                if (t == TT - 1) out_hf[b * OO + o] = y;
            }
        }
        grid_arrive(tgtB);
        grid_wait(tgtB);
    }
}

extern "C" void kernel_launch(void* const* d_in, const int* in_sizes, int n_in,
                              void* d_out, int out_size) {
    (void)in_sizes; (void)n_in; (void)out_size;
    const float* x       = (const float*)d_in[0];
    const float* W_in    = (const float*)d_in[1];
    const float* b_in    = (const float*)d_in[2];
    const float* W_h     = (const float*)d_in[3];
    const float* W_ir    = (const float*)d_in[4];
    const float* b_ir    = (const float*)d_in[5];
    const float* W_hr    = (const float*)d_in[6];
    const float* periods = (const float*)d_in[7];
    const float* shifts  = (const float*)d_in[8];
    float* out = (float*)d_out;

    cudaFuncSetAttribute(cwrnn_kernel,
                         cudaFuncAttributeMaxDynamicSharedMemorySize, DYN_SMEM);
    cwrnn_kernel<<<NBLK, NT, DYN_SMEM>>>(x, W_in, b_in, W_h, W_ir, b_ir, W_hr,
                                         periods, shifts, out);
}